// round 7
// baseline (speedup 1.0000x reference)
#include <cuda_runtime.h>
#include <cuda_bf16.h>

// Causal cumulative normalization along frames.
// TWO consecutive rows per warp; row B addressed as immediate offset from
// row A's base pointers (saves 8 regs -> 64 regs -> 8 blocks/SM, 32 warps).
// Per row per iteration: 256 frames (2 x float4 per lane), 1-chunk prefetch.
// Division-free: out = (x*c - s) * rsqrt(c*(q + eps*c) - s*s).

#define EPSV 1e-4f

constexpr int FRAMES   = 4000;
constexpr int F4       = FRAMES / 4;      // 1000 float4 per row (16000 B offset)
constexpr int NFULL256 = 15;              // 15 * 256 = 3840 frames
// then one 128-frame chunk (3840..3967), then 32-frame tail (3968..3999)

__device__ __forceinline__ void process128(float4 cv, float cbase, int lane,
                                           float& carry_s, float& carry_q,
                                           float4* outp) {
    // per-lane inclusive prefixes over 4 elements
    float s0 = cv.x;
    float s1 = s0 + cv.y;
    float s2 = s1 + cv.z;
    float s3 = s2 + cv.w;
    float q0 = cv.x * cv.x;
    float q1 = fmaf(cv.y, cv.y, q0);
    float q2 = fmaf(cv.z, cv.z, q1);
    float q3 = fmaf(cv.w, cv.w, q2);

    // warp inclusive scan of lane totals
    float ts = s3, tq = q3;
    #pragma unroll
    for (int off = 1; off < 32; off <<= 1) {
        float as = __shfl_up_sync(0xffffffffu, ts, off);
        float aq = __shfl_up_sync(0xffffffffu, tq, off);
        if (lane >= off) { ts += as; tq += aq; }
    }

    float bs = carry_s + (ts - s3);   // exclusive lane base + carry
    float bq = carry_q + (tq - q3);
    carry_s += __shfl_sync(0xffffffffu, ts, 31);
    carry_q += __shfl_sync(0xffffffffu, tq, 31);

    float4 o;
    {
        float c = cbase;
        float s = bs + s0, q = bq + q0;
        float u = fmaf(EPSV, c, q);
        float r = fmaf(c, u, -s * s);
        o.x = fmaf(cv.x, c, -s) * rsqrtf(r);
    }
    {
        float c = cbase + 1.0f;
        float s = bs + s1, q = bq + q1;
        float u = fmaf(EPSV, c, q);
        float r = fmaf(c, u, -s * s);
        o.y = fmaf(cv.y, c, -s) * rsqrtf(r);
    }
    {
        float c = cbase + 2.0f;
        float s = bs + s2, q = bq + q2;
        float u = fmaf(EPSV, c, q);
        float r = fmaf(c, u, -s * s);
        o.z = fmaf(cv.z, c, -s) * rsqrtf(r);
    }
    {
        float c = cbase + 3.0f;
        float s = bs + s3, q = bq + q3;
        float u = fmaf(EPSV, c, q);
        float r = fmaf(c, u, -s * s);
        o.w = fmaf(cv.w, c, -s) * rsqrtf(r);
    }
    __stcs(outp, o);
}

__device__ __forceinline__ void tail32(const float* xr, float* outr, int lane,
                                       float carry_s, float carry_q) {
    int base = NFULL256 * 256 + 128 + lane;   // 3968 + lane
    float xval = __ldcs(xr + base);
    float ts = xval, tq = xval * xval;
    #pragma unroll
    for (int off = 1; off < 32; off <<= 1) {
        float as = __shfl_up_sync(0xffffffffu, ts, off);
        float aq = __shfl_up_sync(0xffffffffu, tq, off);
        if (lane >= off) { ts += as; tq += aq; }
    }
    float c = (float)(base + 1);
    float s = carry_s + ts;
    float q = carry_q + tq;
    float u = fmaf(EPSV, c, q);
    float r = fmaf(c, u, -s * s);
    __stcs(outr + base, fmaf(xval, c, -s) * rsqrtf(r));
}

__global__ __launch_bounds__(128, 8)
void cumnorm_kernel(const float* __restrict__ x, float* __restrict__ out, int pairs) {
    int gw   = (blockIdx.x * blockDim.x + threadIdx.x) >> 5;
    int lane = threadIdx.x & 31;
    if (gw >= pairs) return;

    // single base pointer per array; row B lives at constant offset F4 float4s
    const float4* __restrict__ xa = (const float4*)(x + (long long)(2 * gw) * FRAMES);
    float4*       __restrict__ oa = (float4*)(out + (long long)(2 * gw) * FRAMES);

    float csa = 0.0f, cqa = 0.0f;   // carries row A
    float csb = 0.0f, cqb = 0.0f;   // carries row B

    float clane = (float)(lane * 4 + 1);

    // prefetch first 256-frame chunk of both rows
    float4 a0 = __ldcs(xa + lane);
    float4 a1 = __ldcs(xa + 32 + lane);
    float4 b0 = __ldcs(xa + F4 + lane);
    float4 b1 = __ldcs(xa + F4 + 32 + lane);

    #pragma unroll 1
    for (int it = 0; it < NFULL256; ++it) {
        float4 ca0 = a0, ca1 = a1, cb0 = b0, cb1 = b1;
        if (it + 1 < NFULL256) {
            int nb = (it + 1) * 64 + lane;
            a0 = __ldcs(xa + nb);
            a1 = __ldcs(xa + nb + 32);
            b0 = __ldcs(xa + F4 + nb);
            b1 = __ldcs(xa + F4 + nb + 32);
        } else {
            // prefetch the trailing 128-frame chunks into slot 0
            a0 = __ldcs(xa + NFULL256 * 64 + lane);
            b0 = __ldcs(xa + F4 + NFULL256 * 64 + lane);
        }
        float cbase = (float)(it * 256) + clane;
        process128(ca0, cbase,          lane, csa, cqa, oa + it * 64 + lane);
        process128(cb0, cbase,          lane, csb, cqb, oa + F4 + it * 64 + lane);
        process128(ca1, cbase + 128.0f, lane, csa, cqa, oa + it * 64 + 32 + lane);
        process128(cb1, cbase + 128.0f, lane, csb, cqb, oa + F4 + it * 64 + 32 + lane);
    }

    // trailing 128-frame chunks (frames 3840..3967), prefetched in a0/b0
    process128(a0, 3840.0f + clane, lane, csa, cqa, oa + NFULL256 * 64 + lane);
    process128(b0, 3840.0f + clane, lane, csb, cqb, oa + F4 + NFULL256 * 64 + lane);

    // 32-frame tails (frames 3968..3999)
    tail32((const float*)xa,        (float*)oa,        lane, csa, cqa);
    tail32((const float*)xa + FRAMES, (float*)oa + FRAMES, lane, csb, cqb);
}

extern "C" void kernel_launch(void* const* d_in, const int* in_sizes, int n_in,
                              void* d_out, int out_size) {
    const float* x = (const float*)d_in[0];
    float* out = (float*)d_out;
    int rows  = in_sizes[0] / FRAMES;   // 32*512 = 16384
    int pairs = rows / 2;               // 8192

    constexpr int WARPS_PER_BLOCK = 4;
    int blocks = (pairs + WARPS_PER_BLOCK - 1) / WARPS_PER_BLOCK;
    cumnorm_kernel<<<blocks, WARPS_PER_BLOCK * 32>>>(x, out, pairs);
}